// round 6
// baseline (speedup 1.0000x reference)
#include <cuda_runtime.h>
#include <math.h>

namespace {

constexpr int EMBED     = 20;
constexpr int FEAT      = 560;
constexpr int BATCH_MAX = 16384;
constexpr int CTHREADS  = 512;   // conv: 16 warps = 16 filters

typedef unsigned long long ull;

// ---------------- packed f32x2 helpers (Blackwell FFMA2) ----------------
__device__ __forceinline__ ull pack2(float a, float b) {
  ull r;
  asm("mov.b64 %0, {%1, %2};" : "=l"(r) : "f"(a), "f"(b));
  return r;
}
__device__ __forceinline__ void unpack2(ull v, float& a, float& b) {
  asm("mov.b64 {%0, %1}, %2;" : "=f"(a), "=f"(b) : "l"(v));
}
__device__ __forceinline__ ull fma2(ull a, ull b, ull c) {
  ull d;
  asm("fma.rn.f32x2 %0, %1, %2, %3;" : "=l"(d) : "l"(a), "l"(b), "l"(c));
  return d;
}

// ---------------- global scratch ----------------
__device__ float  g_feat[FEAT * BATCH_MAX];   // transposed [feat][B]
__device__ float2 g_w1p[FEAT * 32];           // MLP W1 pre-pack
__device__ ull    g_wdup[56000];              // conv weights, dup'd, *0.2 folded
// ull offsets per ksize (layout [S][f][c][j] within each segment)
constexpr int WOFF1 = 0;      // 7*16*20*1 = 2240
constexpr int WOFF3 = 2240;   // 6720
constexpr int WOFF5 = 8960;   // 11200
constexpr int WOFF7 = 20160;  // 15680
constexpr int WOFF9 = 35840;  // 20160 -> total 56000

struct ConvParams {
  const float* seq[7];
  const float* Wk[5];
  int B;
};
struct MlpParams {
  const float* lin1_w;
  const float* lin1_b;
  const float* lin2_w;
  const float* lin2_b;
  float* out;
  int B;
};

// smem: x tile only, [c*L+l][33] float2 = (x_b, x_{b+32}); max L = 18
constexpr int CONV_SMEM_BYTES = EMBED * 18 * 33 * 8;   // 95040 -> 2 CTA/SM

// ---- group k={1,3,5}: shared x window, 3 acc arrays ----
template<int L, int T0, int NT>
__device__ __forceinline__ void conv_g135(const ull* __restrict__ sXu,
                                          const ull* __restrict__ w1g,
                                          const ull* __restrict__ w3g,
                                          const ull* __restrict__ w5g,
                                          int lane, float (&mx)[10]) {
  constexpr int XLO = (T0 - 2 > 0) ? (T0 - 2) : 0;
  constexpr int XHI = (T0 + NT + 2 < L) ? (T0 + NT + 2) : L;
  constexpr int NX  = XHI - XLO;
  ull a1[NT], a3[NT], a5[NT];
  #pragma unroll
  for (int t = 0; t < NT; ++t) { a1[t] = 0; a3[t] = 0; a5[t] = 0; }
  for (int c = 0; c < EMBED; ++c) {
    ull xx[NX];
    #pragma unroll
    for (int l = 0; l < NX; ++l) xx[l] = sXu[(c * L + XLO + l) * 33 + lane];
    {  // k = 1
      const ull w = __ldg(w1g + c);
      #pragma unroll
      for (int t = 0; t < NT; ++t) a1[t] = fma2(xx[T0 + t - XLO], w, a1[t]);
    }
    {  // k = 3, pad 1
      ull wt[3];
      #pragma unroll
      for (int j = 0; j < 3; ++j) wt[j] = __ldg(w3g + c * 3 + j);
      #pragma unroll
      for (int t = 0; t < NT; ++t)
        #pragma unroll
        for (int j = 0; j < 3; ++j) {
          const int xi = T0 + t + j - 1;
          if (xi >= 0 && xi < L) a3[t] = fma2(xx[xi - XLO], wt[j], a3[t]);
        }
    }
    {  // k = 5, pad 2
      ull wt[5];
      #pragma unroll
      for (int j = 0; j < 5; ++j) wt[j] = __ldg(w5g + c * 5 + j);
      #pragma unroll
      for (int t = 0; t < NT; ++t)
        #pragma unroll
        for (int j = 0; j < 5; ++j) {
          const int xi = T0 + t + j - 2;
          if (xi >= 0 && xi < L) a5[t] = fma2(xx[xi - XLO], wt[j], a5[t]);
        }
    }
  }
  #pragma unroll
  for (int t = 0; t < NT; ++t) {
    float a, b;
    unpack2(a1[t], a, b); mx[0] = fmaxf(mx[0], a); mx[1] = fmaxf(mx[1], b);
    unpack2(a3[t], a, b); mx[2] = fmaxf(mx[2], a); mx[3] = fmaxf(mx[3], b);
    unpack2(a5[t], a, b); mx[4] = fmaxf(mx[4], a); mx[5] = fmaxf(mx[5], b);
  }
}

// ---- group k={7,9}: shared x window, 2 acc arrays ----
template<int L, int T0, int NT>
__device__ __forceinline__ void conv_g79(const ull* __restrict__ sXu,
                                         const ull* __restrict__ w7g,
                                         const ull* __restrict__ w9g,
                                         int lane, float (&mx)[10]) {
  constexpr int XLO = (T0 - 4 > 0) ? (T0 - 4) : 0;
  constexpr int XHI = (T0 + NT + 4 < L) ? (T0 + NT + 4) : L;
  constexpr int NX  = XHI - XLO;
  ull a7[NT], a9[NT];
  #pragma unroll
  for (int t = 0; t < NT; ++t) { a7[t] = 0; a9[t] = 0; }
  for (int c = 0; c < EMBED; ++c) {
    ull xx[NX];
    #pragma unroll
    for (int l = 0; l < NX; ++l) xx[l] = sXu[(c * L + XLO + l) * 33 + lane];
    {  // k = 7, pad 3
      ull wt[7];
      #pragma unroll
      for (int j = 0; j < 7; ++j) wt[j] = __ldg(w7g + c * 7 + j);
      #pragma unroll
      for (int t = 0; t < NT; ++t)
        #pragma unroll
        for (int j = 0; j < 7; ++j) {
          const int xi = T0 + t + j - 3;
          if (xi >= 0 && xi < L) a7[t] = fma2(xx[xi - XLO], wt[j], a7[t]);
        }
    }
    {  // k = 9, pad 4
      ull wt[9];
      #pragma unroll
      for (int j = 0; j < 9; ++j) wt[j] = __ldg(w9g + c * 9 + j);
      #pragma unroll
      for (int t = 0; t < NT; ++t)
        #pragma unroll
        for (int j = 0; j < 9; ++j) {
          const int xi = T0 + t + j - 4;
          if (xi >= 0 && xi < L) a9[t] = fma2(xx[xi - XLO], wt[j], a9[t]);
        }
    }
  }
  #pragma unroll
  for (int t = 0; t < NT; ++t) {
    float a, b;
    unpack2(a7[t], a, b); mx[6] = fmaxf(mx[6], a); mx[7] = fmaxf(mx[7], b);
    unpack2(a9[t], a, b); mx[8] = fmaxf(mx[8], a); mx[9] = fmaxf(mx[9], b);
  }
}

template<int L, int S>
__device__ void do_seq(const ConvParams& p, float2* sX2,
                       int tid, int lane, int f, int bbase) {
  // stage x: sX2[rem][bp] = (x[bbase+bp], x[bbase+bp+32])  (scale folded in W)
  const float* xg = p.seq[S];
  constexpr int CL = EMBED * L;
  for (int idx = tid; idx < CL * 32; idx += CTHREADS) {
    const int bp  = idx / CL;
    const int rem = idx - bp * CL;
    const int b0  = min(bbase + bp, p.B - 1);
    const int b1  = min(b0 + 32, p.B - 1);
    sX2[rem * 33 + bp] = make_float2(xg[(size_t)b0 * CL + rem],
                                     xg[(size_t)b1 * CL + rem]);
  }
  __syncthreads();
  const ull* sXu = (const ull*)sX2;
  const ull* w1g = g_wdup + WOFF1 + (size_t)(S * 16 + f) * 20;
  const ull* w3g = g_wdup + WOFF3 + (size_t)(S * 16 + f) * 60;
  const ull* w5g = g_wdup + WOFF5 + (size_t)(S * 16 + f) * 100;
  const ull* w7g = g_wdup + WOFF7 + (size_t)(S * 16 + f) * 140;
  const ull* w9g = g_wdup + WOFF9 + (size_t)(S * 16 + f) * 180;

  float mx[10];
  #pragma unroll
  for (int i = 0; i < 10; ++i) mx[i] = 0.f;   // relu folded into init

  constexpr int NT0 = (L < 6) ? L : 6;
  conv_g135<L, 0, NT0>(sXu, w1g, w3g, w5g, lane, mx);
  conv_g79 <L, 0, NT0>(sXu, w7g, w9g, lane, mx);
  if constexpr (L > 6) {
    constexpr int NT1 = (L - 6 < 6) ? (L - 6) : 6;
    conv_g135<L, 6, NT1>(sXu, w1g, w3g, w5g, lane, mx);
    conv_g79 <L, 6, NT1>(sXu, w7g, w9g, lane, mx);
  }
  if constexpr (L > 12) {
    constexpr int NT2 = L - 12;
    conv_g135<L, 12, NT2>(sXu, w1g, w3g, w5g, lane, mx);
    conv_g79 <L, 12, NT2>(sXu, w7g, w9g, lane, mx);
  }

  const int bg0 = min(bbase + lane, p.B - 1);
  const int bg1 = min(bg0 + 32, p.B - 1);
  #pragma unroll
  for (int kidx = 0; kidx < 5; ++kidx) {
    g_feat[(size_t)(S * 80 + kidx * 16 + f) * p.B + bg0] = mx[kidx * 2];
    g_feat[(size_t)(S * 80 + kidx * 16 + f) * p.B + bg1] = mx[kidx * 2 + 1];
  }
}

__global__ __launch_bounds__(CTHREADS, 2) void conv_kernel(ConvParams p) {
  extern __shared__ float smem[];
  float2* sX2 = (float2*)smem;
  const int tid   = threadIdx.x;
  const int lane  = tid & 31;
  const int f     = tid >> 5;          // warp -> one filter
  const int bbase = blockIdx.x * 64;   // 64 batch per CTA (paired lanes)
  switch (blockIdx.y) {
    case 0: do_seq<12, 0>(p, sX2, tid, lane, f, bbase); break;
    case 1: do_seq< 7, 1>(p, sX2, tid, lane, f, bbase); break;
    case 2: do_seq< 8, 2>(p, sX2, tid, lane, f, bbase); break;
    case 3: do_seq<16, 3>(p, sX2, tid, lane, f, bbase); break;
    case 4: do_seq< 6, 4>(p, sX2, tid, lane, f, bbase); break;
    case 5: do_seq< 7, 5>(p, sX2, tid, lane, f, bbase); break;
    case 6: do_seq<18, 6>(p, sX2, tid, lane, f, bbase); break;
  }
}

// ---------------- prep: dup conv weights (fold /5), pack MLP W1 ----------
__global__ void prep_wdup_kernel(const float* __restrict__ w1,
                                 const float* __restrict__ w3,
                                 const float* __restrict__ w5,
                                 const float* __restrict__ w7,
                                 const float* __restrict__ w9) {
  const int idx = blockIdx.x * 256 + threadIdx.x;
  if (idx >= 56000) return;
  float v;
  if      (idx < WOFF3) v = w1[idx - WOFF1];
  else if (idx < WOFF5) v = w3[idx - WOFF3];
  else if (idx < WOFF7) v = w5[idx - WOFF5];
  else if (idx < WOFF9) v = w7[idx - WOFF7];
  else                  v = w9[idx - WOFF9];
  v *= 0.2f;
  g_wdup[idx] = pack2(v, v);
}

__global__ void prep_w1_kernel(const float* __restrict__ w1) {
  const int idx = blockIdx.x * 256 + threadIdx.x;
  if (idx < FEAT * 32) {
    const int i   = idx >> 5;
    const int col = idx & 31;
    g_w1p[idx] = make_float2(w1[(size_t)(2 * col) * FEAT + i],
                             w1[(size_t)(2 * col + 1) * FEAT + i]);
  }
}

// ---------------- MLP: 64 batch per CTA, 2 batch/thread, f32x2 ----------
constexpr int MLP_SMEM_BYTES = 64 * 65 * 4;

__global__ __launch_bounds__(256) void mlp_kernel(MlpParams p) {
  extern __shared__ float sH[];   // [64 batch][65]
  const int tid   = threadIdx.x;
  const int lane  = tid & 31;
  const int g     = tid >> 5;     // warp -> hidden cols g*8 .. g*8+7
  const int bbase = blockIdx.x * 64;
  const int b0 = min(bbase + lane, p.B - 1);
  const int b1 = min(b0 + 32, p.B - 1);

  ull acc0[4], acc1[4];
  #pragma unroll
  for (int pp = 0; pp < 4; ++pp) {
    const ull bia = pack2(p.lin1_b[g * 8 + 2 * pp], p.lin1_b[g * 8 + 2 * pp + 1]);
    acc0[pp] = bia; acc1[pp] = bia;
  }

  const float4* wbase = (const float4*)(g_w1p);
  #pragma unroll 4
  for (int i = 0; i < FEAT; ++i) {
    const float f0 = g_feat[(size_t)i * p.B + b0];
    const float f1 = g_feat[(size_t)i * p.B + b1];
    const ull ff0 = pack2(f0, f0);
    const ull ff1 = pack2(f1, f1);
    const float4 wa = wbase[i * 16 + g * 2];
    const float4 wb = wbase[i * 16 + g * 2 + 1];
    const ull w0  = pack2(wa.x, wa.y);
    const ull w1v = pack2(wa.z, wa.w);
    const ull w2  = pack2(wb.x, wb.y);
    const ull w3  = pack2(wb.z, wb.w);
    acc0[0] = fma2(ff0, w0, acc0[0]);  acc1[0] = fma2(ff1, w0, acc1[0]);
    acc0[1] = fma2(ff0, w1v, acc0[1]); acc1[1] = fma2(ff1, w1v, acc1[1]);
    acc0[2] = fma2(ff0, w2, acc0[2]);  acc1[2] = fma2(ff1, w2, acc1[2]);
    acc0[3] = fma2(ff0, w3, acc0[3]);  acc1[3] = fma2(ff1, w3, acc1[3]);
  }
  #pragma unroll
  for (int pp = 0; pp < 4; ++pp) {
    float a, b;
    unpack2(acc0[pp], a, b);
    sH[lane * 65 + g * 8 + 2 * pp]     = 1.f / (1.f + __expf(-a));
    sH[lane * 65 + g * 8 + 2 * pp + 1] = 1.f / (1.f + __expf(-b));
    unpack2(acc1[pp], a, b);
    sH[(lane + 32) * 65 + g * 8 + 2 * pp]     = 1.f / (1.f + __expf(-a));
    sH[(lane + 32) * 65 + g * 8 + 2 * pp + 1] = 1.f / (1.f + __expf(-b));
  }
  __syncthreads();

  if (tid < 64) {
    const int bgo = bbase + tid;
    if (bgo < p.B) {
      float o = p.lin2_b[0];
      #pragma unroll
      for (int j = 0; j < 64; ++j)
        o = fmaf(sH[tid * 65 + j], __ldg(p.lin2_w + j), o);
      p.out[bgo] = o;
    }
  }
}

} // namespace

extern "C" void kernel_launch(void* const* d_in, const int* in_sizes, int n_in,
                              void* d_out, int out_size) {
  ConvParams cp;
  for (int i = 0; i < 7; ++i) cp.seq[i] = (const float*)d_in[i];
  for (int j = 0; j < 5; ++j) cp.Wk[j] = (const float*)d_in[7 + j];
  cp.B = out_size;

  MlpParams mp;
  mp.lin1_w = (const float*)d_in[12];
  mp.lin1_b = (const float*)d_in[13];
  mp.lin2_w = (const float*)d_in[14];
  mp.lin2_b = (const float*)d_in[15];
  mp.out = (float*)d_out;
  mp.B   = out_size;

  static bool attr_set = false;
  if (!attr_set) {
    cudaFuncSetAttribute(conv_kernel,
                         cudaFuncAttributeMaxDynamicSharedMemorySize, CONV_SMEM_BYTES);
    attr_set = true;
  }

  const int tiles64 = (cp.B + 63) / 64;
  prep_wdup_kernel<<<(56000 + 255) / 256, 256>>>(cp.Wk[0], cp.Wk[1], cp.Wk[2],
                                                 cp.Wk[3], cp.Wk[4]);
  prep_w1_kernel<<<(FEAT * 32 + 255) / 256, 256>>>(mp.lin1_w);
  dim3 cgrid(tiles64, 7);
  conv_kernel<<<cgrid, CTHREADS, CONV_SMEM_BYTES>>>(cp);
  mlp_kernel<<<tiles64, 256, MLP_SMEM_BYTES>>>(mp);
}

// round 7
// speedup vs baseline: 1.2030x; 1.2030x over previous
#include <cuda_runtime.h>
#include <math.h>

namespace {

constexpr int EMBED     = 20;
constexpr int THREADS   = 256;   // conv CTA
constexpr int FEAT      = 560;
constexpr int BATCH_MAX = 16384;

typedef unsigned long long ull;

// ---------------- packed f32x2 helpers (Blackwell FFMA2) ----------------
__device__ __forceinline__ ull pack2(float a, float b) {
  ull r;
  asm("mov.b64 %0, {%1, %2};" : "=l"(r) : "f"(a), "f"(b));
  return r;
}
__device__ __forceinline__ void unpack2(ull v, float& a, float& b) {
  asm("mov.b64 {%0, %1}, %2;" : "=f"(a), "=f"(b) : "l"(v));
}
__device__ __forceinline__ ull fma2(ull a, ull b, ull c) {
  ull d;
  asm("fma.rn.f32x2 %0, %1, %2, %3;" : "=l"(d) : "l"(a), "l"(b), "l"(c));
  return d;
}

// ---------------- global scratch ----------------
__device__ float  g_feat[FEAT * BATCH_MAX];   // transposed [feat][B]
__device__ float2 g_w1p[FEAT * 32];           // [i][col]=(W1[2c][i],W1[2c+1][i])

struct ConvParams {
  const float* seq[7];
  const float* Wk[5];
  int B;
};
struct MlpParams {
  const float* lin1_w;
  const float* lin1_b;
  const float* lin2_w;
  const float* lin2_b;
  float* out;
  int B;
};

// smem: x tile only, [c*L+l][33] float2 = (x_b, x_{b+32}); max L = 18
constexpr int CONV_SMEM_BYTES = EMBED * 18 * 33 * 8;   // 95040

// ======================= CONV (R5 verbatim — measured ~357us) ===========
template<int L, int K, int T0, int T1>
__device__ __forceinline__ void conv_chunk(const ull* __restrict__ sXu,
                                           const float* __restrict__ wg,
                                           int lane, float& m0, float& m1) {
  constexpr int PAD = (K - 1) / 2;
  constexpr int XLO = (T0 - PAD > 0) ? (T0 - PAD) : 0;
  constexpr int XHI = (T1 + PAD < L) ? (T1 + PAD) : L;   // exclusive
  constexpr int NX  = XHI - XLO;
  constexpr int NT  = T1 - T0;
  ull acc[NT];
  #pragma unroll
  for (int t = 0; t < NT; ++t) acc[t] = 0ULL;
  #pragma unroll 2
  for (int c = 0; c < EMBED; ++c) {
    ull xx[NX];
    #pragma unroll
    for (int l = 0; l < NX; ++l)
      xx[l] = sXu[(c * L + XLO + l) * 33 + lane];        // LDS.64, pairs
    ull wt[K];
    #pragma unroll
    for (int j = 0; j < K; ++j) {
      const float wv = __ldg(wg + c * K + j);            // warp-uniform, L1
      wt[j] = pack2(wv, wv);
    }
    #pragma unroll
    for (int t = T0; t < T1; ++t) {
      #pragma unroll
      for (int j = 0; j < K; ++j) {
        const int xi = t + j - PAD;                      // compile-time pred
        if (xi >= 0 && xi < L)
          acc[t - T0] = fma2(xx[xi - XLO], wt[j], acc[t - T0]);
      }
    }
  }
  #pragma unroll
  for (int t = 0; t < NT; ++t) {
    float a, b; unpack2(acc[t], a, b);
    m0 = fmaxf(m0, a); m1 = fmaxf(m1, b);                // relu+gmax
  }
}

template<int L, int K>
__device__ __forceinline__ void conv_all(const ull* __restrict__ sXu,
                                         const float* __restrict__ wg,
                                         int lane, float& m0, float& m1) {
  if constexpr (L <= 9) {
    conv_chunk<L, K, 0, L>(sXu, wg, lane, m0, m1);
  } else if constexpr (L <= 12) {
    conv_chunk<L, K, 0, 6>(sXu, wg, lane, m0, m1);
    conv_chunk<L, K, 6, L>(sXu, wg, lane, m0, m1);
  } else {
    conv_chunk<L, K, 0, 6>(sXu, wg, lane, m0, m1);
    conv_chunk<L, K, 6, 12>(sXu, wg, lane, m0, m1);
    conv_chunk<L, K, 12, L>(sXu, wg, lane, m0, m1);
  }
}

template<int L, int S>
__device__ void do_seq(const ConvParams& p, float2* sX2,
                       int tid, int lane, int w, int bbase) {
  const float* xg = p.seq[S];
  constexpr int CL = EMBED * L;
  for (int idx = tid; idx < CL * 32; idx += THREADS) {
    const int bp  = idx / CL;
    const int rem = idx - bp * CL;
    const int b0  = min(bbase + bp, p.B - 1);
    const int b1  = min(b0 + 32, p.B - 1);
    sX2[rem * 33 + bp] = make_float2(xg[(size_t)b0 * CL + rem] * 0.2f,
                                     xg[(size_t)b1 * CL + rem] * 0.2f);
  }
  __syncthreads();
  const ull* sXu = (const ull*)sX2;
  const int bg0 = min(bbase + lane, p.B - 1);
  const int bg1 = min(bg0 + 32, p.B - 1);

  #pragma unroll
  for (int fi = 0; fi < 2; ++fi) {
    const int f = 2 * w + fi;
    {
      float m0 = 0.f, m1 = 0.f;
      conv_all<L, 1>(sXu, p.Wk[0] + ((size_t)S * 16 + f) * EMBED * 1, lane, m0, m1);
      g_feat[(size_t)(S * 80 + 0 + f) * p.B + bg0] = m0;
      g_feat[(size_t)(S * 80 + 0 + f) * p.B + bg1] = m1;
    }
    {
      float m0 = 0.f, m1 = 0.f;
      conv_all<L, 3>(sXu, p.Wk[1] + ((size_t)S * 16 + f) * EMBED * 3, lane, m0, m1);
      g_feat[(size_t)(S * 80 + 16 + f) * p.B + bg0] = m0;
      g_feat[(size_t)(S * 80 + 16 + f) * p.B + bg1] = m1;
    }
    {
      float m0 = 0.f, m1 = 0.f;
      conv_all<L, 5>(sXu, p.Wk[2] + ((size_t)S * 16 + f) * EMBED * 5, lane, m0, m1);
      g_feat[(size_t)(S * 80 + 32 + f) * p.B + bg0] = m0;
      g_feat[(size_t)(S * 80 + 32 + f) * p.B + bg1] = m1;
    }
    {
      float m0 = 0.f, m1 = 0.f;
      conv_all<L, 7>(sXu, p.Wk[3] + ((size_t)S * 16 + f) * EMBED * 7, lane, m0, m1);
      g_feat[(size_t)(S * 80 + 48 + f) * p.B + bg0] = m0;
      g_feat[(size_t)(S * 80 + 48 + f) * p.B + bg1] = m1;
    }
    {
      float m0 = 0.f, m1 = 0.f;
      conv_all<L, 9>(sXu, p.Wk[4] + ((size_t)S * 16 + f) * EMBED * 9, lane, m0, m1);
      g_feat[(size_t)(S * 80 + 64 + f) * p.B + bg0] = m0;
      g_feat[(size_t)(S * 80 + 64 + f) * p.B + bg1] = m1;
    }
  }
}

__global__ __launch_bounds__(THREADS, 2) void conv_kernel(ConvParams p) {
  extern __shared__ float smem[];
  float2* sX2 = (float2*)smem;
  const int tid   = threadIdx.x;
  const int lane  = tid & 31;
  const int w     = tid >> 5;          // warp -> filter pair (2w, 2w+1)
  const int bbase = blockIdx.x * 64;   // 64 batch per CTA (paired)
  switch (blockIdx.y) {
    case 0: do_seq<12, 0>(p, sX2, tid, lane, w, bbase); break;
    case 1: do_seq< 7, 1>(p, sX2, tid, lane, w, bbase); break;
    case 2: do_seq< 8, 2>(p, sX2, tid, lane, w, bbase); break;
    case 3: do_seq<16, 3>(p, sX2, tid, lane, w, bbase); break;
    case 4: do_seq< 6, 4>(p, sX2, tid, lane, w, bbase); break;
    case 5: do_seq< 7, 5>(p, sX2, tid, lane, w, bbase); break;
    case 6: do_seq<18, 6>(p, sX2, tid, lane, w, bbase); break;
  }
}

// ---------------- W1 pre-pack ----------------
__global__ void prep_w1_kernel(const float* __restrict__ w1) {
  const int idx = blockIdx.x * 256 + threadIdx.x;
  if (idx < FEAT * 32) {
    const int i   = idx >> 5;
    const int col = idx & 31;
    g_w1p[idx] = make_float2(w1[(size_t)(2 * col) * FEAT + i],
                             w1[(size_t)(2 * col + 1) * FEAT + i]);
  }
}

// ============ MLP v3: 32 batch/CTA, 512 thr, split-K over features =======
// warp (h,g): h = feature half (280 each), g = hidden col group (8 cols).
constexpr int MTHREADS = 512;
constexpr int MLP_SMEM_BYTES = 2 * 32 * 65 * 4;   // partials + sigmoid out

__global__ __launch_bounds__(MTHREADS) void mlp_kernel(MlpParams p) {
  extern __shared__ float smem[];
  float* sP1 = smem;             // [32][65] h=1 partials
  float* sH  = smem + 32 * 65;   // [32][65] sigmoid(h) outputs
  const int tid  = threadIdx.x;
  const int lane = tid & 31;
  const int wid  = tid >> 5;     // 0..15
  const int h    = wid >> 3;     // feature half
  const int g    = wid & 7;      // col group
  const int bbase = blockIdx.x * 32;
  const int b = min(bbase + lane, p.B - 1);

  ull acc[4];
  #pragma unroll
  for (int pp = 0; pp < 4; ++pp)
    acc[pp] = (h == 0)
      ? pack2(p.lin1_b[g * 8 + 2 * pp], p.lin1_b[g * 8 + 2 * pp + 1])
      : 0ULL;

  const float4* wbase = (const float4*)(g_w1p);
  const int i0 = h * 280;
  #pragma unroll 4
  for (int ii = 0; ii < 280; ++ii) {
    const int i = i0 + ii;
    const float f = g_feat[(size_t)i * p.B + b];   // coalesced
    const ull ff = pack2(f, f);
    const float4 wa = wbase[i * 16 + g * 2];       // uniform LDG.128
    const float4 wb = wbase[i * 16 + g * 2 + 1];
    acc[0] = fma2(ff, pack2(wa.x, wa.y), acc[0]);
    acc[1] = fma2(ff, pack2(wa.z, wa.w), acc[1]);
    acc[2] = fma2(ff, pack2(wb.x, wb.y), acc[2]);
    acc[3] = fma2(ff, pack2(wb.z, wb.w), acc[3]);
  }

  if (h == 1) {
    #pragma unroll
    for (int pp = 0; pp < 4; ++pp) {
      float a, bb; unpack2(acc[pp], a, bb);
      sP1[lane * 65 + g * 8 + 2 * pp]     = a;
      sP1[lane * 65 + g * 8 + 2 * pp + 1] = bb;
    }
  }
  __syncthreads();
  if (h == 0) {
    #pragma unroll
    for (int pp = 0; pp < 4; ++pp) {
      float a, bb; unpack2(acc[pp], a, bb);
      a  += sP1[lane * 65 + g * 8 + 2 * pp];
      bb += sP1[lane * 65 + g * 8 + 2 * pp + 1];
      sH[lane * 65 + g * 8 + 2 * pp]     = 1.f / (1.f + __expf(-a));
      sH[lane * 65 + g * 8 + 2 * pp + 1] = 1.f / (1.f + __expf(-bb));
    }
  }
  __syncthreads();

  if (tid < 32) {
    const int bgo = bbase + tid;
    if (bgo < p.B) {
      float o = p.lin2_b[0];
      #pragma unroll
      for (int j = 0; j < 64; ++j)
        o = fmaf(sH[tid * 65 + j], __ldg(p.lin2_w + j), o);
      p.out[bgo] = o;
    }
  }
}

} // namespace

extern "C" void kernel_launch(void* const* d_in, const int* in_sizes, int n_in,
                              void* d_out, int out_size) {
  ConvParams cp;
  for (int i = 0; i < 7; ++i) cp.seq[i] = (const float*)d_in[i];
  for (int j = 0; j < 5; ++j) cp.Wk[j] = (const float*)d_in[7 + j];
  cp.B = out_size;

  MlpParams mp;
  mp.lin1_w = (const float*)d_in[12];
  mp.lin1_b = (const float*)d_in[13];
  mp.lin2_w = (const float*)d_in[14];
  mp.lin2_b = (const float*)d_in[15];
  mp.out = (float*)d_out;
  mp.B   = out_size;

  static bool attr_set = false;
  if (!attr_set) {
    cudaFuncSetAttribute(conv_kernel,
                         cudaFuncAttributeMaxDynamicSharedMemorySize, CONV_SMEM_BYTES);
    attr_set = true;
  }

  const int tiles64 = (cp.B + 63) / 64;
  const int tiles32 = (cp.B + 31) / 32;
  prep_w1_kernel<<<(FEAT * 32 + 255) / 256, 256>>>(mp.lin1_w);
  dim3 cgrid(tiles64, 7);
  conv_kernel<<<cgrid, THREADS, CONV_SMEM_BYTES>>>(cp);
  mlp_kernel<<<tiles32, MTHREADS, MLP_SMEM_BYTES>>>(mp);
}

// round 8
// speedup vs baseline: 1.4574x; 1.2115x over previous
#include <cuda_runtime.h>
#include <math.h>

namespace {

constexpr int EMBED     = 20;
constexpr int THREADS   = 256;   // conv CTA
constexpr int FEAT      = 560;
constexpr int BATCH_MAX = 16384;

typedef unsigned long long ull;

// ---------------- packed f32x2 helpers (Blackwell FFMA2) ----------------
__device__ __forceinline__ ull pack2(float a, float b) {
  ull r;
  asm("mov.b64 %0, {%1, %2};" : "=l"(r) : "f"(a), "f"(b));
  return r;
}
__device__ __forceinline__ void unpack2(ull v, float& a, float& b) {
  asm("mov.b64 {%0, %1}, %2;" : "=f"(a), "=f"(b) : "l"(v));
}
__device__ __forceinline__ ull fma2(ull a, ull b, ull c) {
  ull d;
  asm("fma.rn.f32x2 %0, %1, %2, %3;" : "=l"(d) : "l"(a), "l"(b), "l"(c));
  return d;
}

// ---------------- global scratch ----------------
__device__ float  g_feat[FEAT * BATCH_MAX];   // transposed [feat][B]
__device__ float2 g_w1p[FEAT * 32];           // [i][col]=(W1[2c][i],W1[2c+1][i])

struct ConvParams {
  const float* seq[7];
  const float* Wk[5];
  int B;
};
struct MlpParams {
  const float* lin1_w;
  const float* lin1_b;
  const float* lin2_w;
  const float* lin2_b;
  float* out;
  int B;
};

// smem: x tile only, [c*L+l][33] float2 = (x_b, x_{b+32}); max L = 18
constexpr int CONV_SMEM_BYTES = EMBED * 18 * 33 * 8;   // 95040

// ======================= CONV (R5 verbatim — measured ~357us) ===========
template<int L, int K, int T0, int T1>
__device__ __forceinline__ void conv_chunk(const ull* __restrict__ sXu,
                                           const float* __restrict__ wg,
                                           int lane, float& m0, float& m1) {
  constexpr int PAD = (K - 1) / 2;
  constexpr int XLO = (T0 - PAD > 0) ? (T0 - PAD) : 0;
  constexpr int XHI = (T1 + PAD < L) ? (T1 + PAD) : L;   // exclusive
  constexpr int NX  = XHI - XLO;
  constexpr int NT  = T1 - T0;
  ull acc[NT];
  #pragma unroll
  for (int t = 0; t < NT; ++t) acc[t] = 0ULL;
  #pragma unroll 2
  for (int c = 0; c < EMBED; ++c) {
    ull xx[NX];
    #pragma unroll
    for (int l = 0; l < NX; ++l)
      xx[l] = sXu[(c * L + XLO + l) * 33 + lane];        // LDS.64, pairs
    ull wt[K];
    #pragma unroll
    for (int j = 0; j < K; ++j) {
      const float wv = __ldg(wg + c * K + j);            // warp-uniform, L1
      wt[j] = pack2(wv, wv);
    }
    #pragma unroll
    for (int t = T0; t < T1; ++t) {
      #pragma unroll
      for (int j = 0; j < K; ++j) {
        const int xi = t + j - PAD;                      // compile-time pred
        if (xi >= 0 && xi < L)
          acc[t - T0] = fma2(xx[xi - XLO], wt[j], acc[t - T0]);
      }
    }
  }
  #pragma unroll
  for (int t = 0; t < NT; ++t) {
    float a, b; unpack2(acc[t], a, b);
    m0 = fmaxf(m0, a); m1 = fmaxf(m1, b);                // relu+gmax
  }
}

template<int L, int K>
__device__ __forceinline__ void conv_all(const ull* __restrict__ sXu,
                                         const float* __restrict__ wg,
                                         int lane, float& m0, float& m1) {
  if constexpr (L <= 9) {
    conv_chunk<L, K, 0, L>(sXu, wg, lane, m0, m1);
  } else if constexpr (L <= 12) {
    conv_chunk<L, K, 0, 6>(sXu, wg, lane, m0, m1);
    conv_chunk<L, K, 6, L>(sXu, wg, lane, m0, m1);
  } else {
    conv_chunk<L, K, 0, 6>(sXu, wg, lane, m0, m1);
    conv_chunk<L, K, 6, 12>(sXu, wg, lane, m0, m1);
    conv_chunk<L, K, 12, L>(sXu, wg, lane, m0, m1);
  }
}

template<int L, int S>
__device__ void do_seq(const ConvParams& p, float2* sX2,
                       int tid, int lane, int w, int bbase) {
  const float* xg = p.seq[S];
  constexpr int CL = EMBED * L;
  for (int idx = tid; idx < CL * 32; idx += THREADS) {
    const int bp  = idx / CL;
    const int rem = idx - bp * CL;
    const int b0  = min(bbase + bp, p.B - 1);
    const int b1  = min(b0 + 32, p.B - 1);
    sX2[rem * 33 + bp] = make_float2(xg[(size_t)b0 * CL + rem] * 0.2f,
                                     xg[(size_t)b1 * CL + rem] * 0.2f);
  }
  __syncthreads();
  const ull* sXu = (const ull*)sX2;
  const int bg0 = min(bbase + lane, p.B - 1);
  const int bg1 = min(bg0 + 32, p.B - 1);

  #pragma unroll
  for (int fi = 0; fi < 2; ++fi) {
    const int f = 2 * w + fi;
    {
      float m0 = 0.f, m1 = 0.f;
      conv_all<L, 1>(sXu, p.Wk[0] + ((size_t)S * 16 + f) * EMBED * 1, lane, m0, m1);
      g_feat[(size_t)(S * 80 + 0 + f) * p.B + bg0] = m0;
      g_feat[(size_t)(S * 80 + 0 + f) * p.B + bg1] = m1;
    }
    {
      float m0 = 0.f, m1 = 0.f;
      conv_all<L, 3>(sXu, p.Wk[1] + ((size_t)S * 16 + f) * EMBED * 3, lane, m0, m1);
      g_feat[(size_t)(S * 80 + 16 + f) * p.B + bg0] = m0;
      g_feat[(size_t)(S * 80 + 16 + f) * p.B + bg1] = m1;
    }
    {
      float m0 = 0.f, m1 = 0.f;
      conv_all<L, 5>(sXu, p.Wk[2] + ((size_t)S * 16 + f) * EMBED * 5, lane, m0, m1);
      g_feat[(size_t)(S * 80 + 32 + f) * p.B + bg0] = m0;
      g_feat[(size_t)(S * 80 + 32 + f) * p.B + bg1] = m1;
    }
    {
      float m0 = 0.f, m1 = 0.f;
      conv_all<L, 7>(sXu, p.Wk[3] + ((size_t)S * 16 + f) * EMBED * 7, lane, m0, m1);
      g_feat[(size_t)(S * 80 + 48 + f) * p.B + bg0] = m0;
      g_feat[(size_t)(S * 80 + 48 + f) * p.B + bg1] = m1;
    }
    {
      float m0 = 0.f, m1 = 0.f;
      conv_all<L, 9>(sXu, p.Wk[4] + ((size_t)S * 16 + f) * EMBED * 9, lane, m0, m1);
      g_feat[(size_t)(S * 80 + 64 + f) * p.B + bg0] = m0;
      g_feat[(size_t)(S * 80 + 64 + f) * p.B + bg1] = m1;
    }
  }
}

__global__ __launch_bounds__(THREADS, 2) void conv_kernel(ConvParams p) {
  extern __shared__ float smem[];
  float2* sX2 = (float2*)smem;
  const int tid   = threadIdx.x;
  const int lane  = tid & 31;
  const int w     = tid >> 5;          // warp -> filter pair (2w, 2w+1)
  const int bbase = blockIdx.x * 64;   // 64 batch per CTA (paired)
  switch (blockIdx.y) {
    case 0: do_seq<12, 0>(p, sX2, tid, lane, w, bbase); break;
    case 1: do_seq< 7, 1>(p, sX2, tid, lane, w, bbase); break;
    case 2: do_seq< 8, 2>(p, sX2, tid, lane, w, bbase); break;
    case 3: do_seq<16, 3>(p, sX2, tid, lane, w, bbase); break;
    case 4: do_seq< 6, 4>(p, sX2, tid, lane, w, bbase); break;
    case 5: do_seq< 7, 5>(p, sX2, tid, lane, w, bbase); break;
    case 6: do_seq<18, 6>(p, sX2, tid, lane, w, bbase); break;
  }
}

// ---------------- W1 pre-pack ----------------
__global__ void prep_w1_kernel(const float* __restrict__ w1) {
  const int idx = blockIdx.x * 256 + threadIdx.x;
  if (idx < FEAT * 32) {
    const int i   = idx >> 5;
    const int col = idx & 31;
    g_w1p[idx] = make_float2(w1[(size_t)(2 * col) * FEAT + i],
                             w1[(size_t)(2 * col + 1) * FEAT + i]);
  }
}

// ====== MLP v4: 32 batch/CTA, 512 thr, split-K + 8-wide feature prefetch ==
constexpr int MTHREADS = 512;
constexpr int MLP_SMEM_BYTES = 2 * 32 * 65 * 4;   // partials + sigmoid out

__global__ __launch_bounds__(MTHREADS) void mlp_kernel(MlpParams p) {
  extern __shared__ float smem[];
  float* sP1 = smem;             // [32][65] h=1 partials
  float* sH  = smem + 32 * 65;   // [32][65] sigmoid(h) outputs
  const int tid  = threadIdx.x;
  const int lane = tid & 31;
  const int wid  = tid >> 5;     // 0..15
  const int h    = wid >> 3;     // feature half
  const int g    = wid & 7;      // col group
  const int bbase = blockIdx.x * 32;
  const int b = min(bbase + lane, p.B - 1);

  ull acc[4];
  #pragma unroll
  for (int pp = 0; pp < 4; ++pp)
    acc[pp] = (h == 0)
      ? pack2(p.lin1_b[g * 8 + 2 * pp], p.lin1_b[g * 8 + 2 * pp + 1])
      : 0ULL;

  const float4* wbase = (const float4*)(g_w1p);
  const float*  fptr  = g_feat + (size_t)(h * 280) * p.B + b;
  const int i0 = h * 280;

  // 280 features in 35 groups of 8: batch 8 independent LDGs, then compute.
  for (int oo = 0; oo < 280; oo += 8) {
    float fb[8];
    #pragma unroll
    for (int k = 0; k < 8; ++k)
      fb[k] = __ldg(fptr + (size_t)(oo + k) * p.B);      // 8 loads in flight
    #pragma unroll
    for (int k = 0; k < 8; ++k) {
      const int i = i0 + oo + k;
      const ull ff = pack2(fb[k], fb[k]);
      const float4 wa = wbase[i * 16 + g * 2];           // uniform, L1-hot
      const float4 wb = wbase[i * 16 + g * 2 + 1];
      acc[0] = fma2(ff, pack2(wa.x, wa.y), acc[0]);
      acc[1] = fma2(ff, pack2(wa.z, wa.w), acc[1]);
      acc[2] = fma2(ff, pack2(wb.x, wb.y), acc[2]);
      acc[3] = fma2(ff, pack2(wb.z, wb.w), acc[3]);
    }
  }

  if (h == 1) {
    #pragma unroll
    for (int pp = 0; pp < 4; ++pp) {
      float a, bb; unpack2(acc[pp], a, bb);
      sP1[lane * 65 + g * 8 + 2 * pp]     = a;
      sP1[lane * 65 + g * 8 + 2 * pp + 1] = bb;
    }
  }
  __syncthreads();
  if (h == 0) {
    #pragma unroll
    for (int pp = 0; pp < 4; ++pp) {
      float a, bb; unpack2(acc[pp], a, bb);
      a  += sP1[lane * 65 + g * 8 + 2 * pp];
      bb += sP1[lane * 65 + g * 8 + 2 * pp + 1];
      sH[lane * 65 + g * 8 + 2 * pp]     = 1.f / (1.f + __expf(-a));
      sH[lane * 65 + g * 8 + 2 * pp + 1] = 1.f / (1.f + __expf(-bb));
    }
  }
  __syncthreads();

  if (tid < 32) {
    const int bgo = bbase + tid;
    if (bgo < p.B) {
      float o = p.lin2_b[0];
      #pragma unroll
      for (int j = 0; j < 64; ++j)
        o = fmaf(sH[tid * 65 + j], __ldg(p.lin2_w + j), o);
      p.out[bgo] = o;
    }
  }
}

} // namespace

extern "C" void kernel_launch(void* const* d_in, const int* in_sizes, int n_in,
                              void* d_out, int out_size) {
  ConvParams cp;
  for (int i = 0; i < 7; ++i) cp.seq[i] = (const float*)d_in[i];
  for (int j = 0; j < 5; ++j) cp.Wk[j] = (const float*)d_in[7 + j];
  cp.B = out_size;

  MlpParams mp;
  mp.lin1_w = (const float*)d_in[12];
  mp.lin1_b = (const float*)d_in[13];
  mp.lin2_w = (const float*)d_in[14];
  mp.lin2_b = (const float*)d_in[15];
  mp.out = (float*)d_out;
  mp.B   = out_size;

  static bool attr_set = false;
  if (!attr_set) {
    cudaFuncSetAttribute(conv_kernel,
                         cudaFuncAttributeMaxDynamicSharedMemorySize, CONV_SMEM_BYTES);
    attr_set = true;
  }

  const int tiles64 = (cp.B + 63) / 64;
  const int tiles32 = (cp.B + 31) / 32;
  prep_w1_kernel<<<(FEAT * 32 + 255) / 256, 256>>>(mp.lin1_w);
  dim3 cgrid(tiles64, 7);
  conv_kernel<<<cgrid, THREADS, CONV_SMEM_BYTES>>>(cp);
  mlp_kernel<<<tiles32, MTHREADS, MLP_SMEM_BYTES>>>(mp);
}

// round 9
// speedup vs baseline: 1.5040x; 1.0320x over previous
#include <cuda_runtime.h>
#include <math.h>

namespace {

constexpr int EMBED     = 20;
constexpr int THREADS   = 256;   // conv CTA: 8 warps = 8 filter pairs
constexpr int FEAT      = 560;
constexpr int BATCH_MAX = 16384;

typedef unsigned long long ull;

// ---------------- packed f32x2 helpers (Blackwell FFMA2) ----------------
__device__ __forceinline__ ull pack2(float a, float b) {
  ull r;
  asm("mov.b64 %0, {%1, %2};" : "=l"(r) : "f"(a), "f"(b));
  return r;
}
__device__ __forceinline__ void unpack2(ull v, float& a, float& b) {
  asm("mov.b64 {%0, %1}, %2;" : "=f"(a), "=f"(b) : "l"(v));
}
__device__ __forceinline__ ull fma2(ull a, ull b, ull c) {
  ull d;
  asm("fma.rn.f32x2 %0, %1, %2, %3;" : "=l"(d) : "l"(a), "l"(b), "l"(c));
  return d;
}

// ---------------- global scratch ----------------
__device__ float  g_feat[FEAT * BATCH_MAX];   // transposed [feat][B]
__device__ float2 g_w1p[FEAT * 32];           // MLP W1 pre-pack
__device__ ull    g_wdup[56000];              // conv weights dup'd, *0.2 folded
constexpr int WOFF1 = 0;      // [S][f][c][j], 7*16*20*k each
constexpr int WOFF3 = 2240;
constexpr int WOFF5 = 8960;
constexpr int WOFF7 = 20160;
constexpr int WOFF9 = 35840;

struct ConvParams {
  const float* seq[7];
  const float* Wk[5];
  int B;
};
struct MlpParams {
  const float* lin1_w;
  const float* lin1_b;
  const float* lin2_w;
  const float* lin2_b;
  float* out;
  int B;
};

// smem: x tile, [c*L+l][33] float2 = (x_b, x_{b+32}); max L = 18
constexpr int CONV_SMEM_BYTES = EMBED * 18 * 33 * 8;   // 95040

// ======== conv group k={1,3,5}: one shared x window (pad 2) ========
template<int L, int T0, int NT>
__device__ __forceinline__ void conv_g135(const ull* __restrict__ sXu,
                                          const ull* __restrict__ w1g,
                                          const ull* __restrict__ w3g,
                                          const ull* __restrict__ w5g,
                                          int lane, float (&mx)[10]) {
  constexpr int XLO = (T0 - 2 > 0) ? (T0 - 2) : 0;
  constexpr int XHI = (T0 + NT + 2 < L) ? (T0 + NT + 2) : L;
  constexpr int NX  = XHI - XLO;
  ull a1[NT], a3[NT], a5[NT];
  #pragma unroll
  for (int t = 0; t < NT; ++t) { a1[t] = 0; a3[t] = 0; a5[t] = 0; }
  for (int c = 0; c < EMBED; ++c) {
    ull xx[NX];
    #pragma unroll
    for (int l = 0; l < NX; ++l) xx[l] = sXu[(c * L + XLO + l) * 33 + lane];
    {
      const ull w = __ldg(w1g + c);
      #pragma unroll
      for (int t = 0; t < NT; ++t) a1[t] = fma2(xx[T0 + t - XLO], w, a1[t]);
    }
    {
      ull wt[3];
      #pragma unroll
      for (int j = 0; j < 3; ++j) wt[j] = __ldg(w3g + c * 3 + j);
      #pragma unroll
      for (int t = 0; t < NT; ++t)
        #pragma unroll
        for (int j = 0; j < 3; ++j) {
          const int xi = T0 + t + j - 1;
          if (xi >= 0 && xi < L) a3[t] = fma2(xx[xi - XLO], wt[j], a3[t]);
        }
    }
    {
      ull wt[5];
      #pragma unroll
      for (int j = 0; j < 5; ++j) wt[j] = __ldg(w5g + c * 5 + j);
      #pragma unroll
      for (int t = 0; t < NT; ++t)
        #pragma unroll
        for (int j = 0; j < 5; ++j) {
          const int xi = T0 + t + j - 2;
          if (xi >= 0 && xi < L) a5[t] = fma2(xx[xi - XLO], wt[j], a5[t]);
        }
    }
  }
  #pragma unroll
  for (int t = 0; t < NT; ++t) {
    float a, b;
    unpack2(a1[t], a, b); mx[0] = fmaxf(mx[0], a); mx[1] = fmaxf(mx[1], b);
    unpack2(a3[t], a, b); mx[2] = fmaxf(mx[2], a); mx[3] = fmaxf(mx[3], b);
    unpack2(a5[t], a, b); mx[4] = fmaxf(mx[4], a); mx[5] = fmaxf(mx[5], b);
  }
}

// ======== conv group k={7,9}: one shared x window (pad 4) ========
template<int L, int T0, int NT>
__device__ __forceinline__ void conv_g79(const ull* __restrict__ sXu,
                                         const ull* __restrict__ w7g,
                                         const ull* __restrict__ w9g,
                                         int lane, float (&mx)[10]) {
  constexpr int XLO = (T0 - 4 > 0) ? (T0 - 4) : 0;
  constexpr int XHI = (T0 + NT + 4 < L) ? (T0 + NT + 4) : L;
  constexpr int NX  = XHI - XLO;
  ull a7[NT], a9[NT];
  #pragma unroll
  for (int t = 0; t < NT; ++t) { a7[t] = 0; a9[t] = 0; }
  for (int c = 0; c < EMBED; ++c) {
    ull xx[NX];
    #pragma unroll
    for (int l = 0; l < NX; ++l) xx[l] = sXu[(c * L + XLO + l) * 33 + lane];
    {
      ull wt[7];
      #pragma unroll
      for (int j = 0; j < 7; ++j) wt[j] = __ldg(w7g + c * 7 + j);
      #pragma unroll
      for (int t = 0; t < NT; ++t)
        #pragma unroll
        for (int j = 0; j < 7; ++j) {
          const int xi = T0 + t + j - 3;
          if (xi >= 0 && xi < L) a7[t] = fma2(xx[xi - XLO], wt[j], a7[t]);
        }
    }
    {
      ull wt[9];
      #pragma unroll
      for (int j = 0; j < 9; ++j) wt[j] = __ldg(w9g + c * 9 + j);
      #pragma unroll
      for (int t = 0; t < NT; ++t)
        #pragma unroll
        for (int j = 0; j < 9; ++j) {
          const int xi = T0 + t + j - 4;
          if (xi >= 0 && xi < L) a9[t] = fma2(xx[xi - XLO], wt[j], a9[t]);
        }
    }
  }
  #pragma unroll
  for (int t = 0; t < NT; ++t) {
    float a, b;
    unpack2(a7[t], a, b); mx[6] = fmaxf(mx[6], a); mx[7] = fmaxf(mx[7], b);
    unpack2(a9[t], a, b); mx[8] = fmaxf(mx[8], a); mx[9] = fmaxf(mx[9], b);
  }
}

// chunk dispatchers — bounded register arrays per chunk
template<int L>
__device__ __forceinline__ void conv135_all(const ull* sXu, const ull* w1g,
                                            const ull* w3g, const ull* w5g,
                                            int lane, float (&mx)[10]) {
  if constexpr (L <= 8) {
    conv_g135<L, 0, L>(sXu, w1g, w3g, w5g, lane, mx);
  } else if constexpr (L <= 12) {
    conv_g135<L, 0, L / 2>(sXu, w1g, w3g, w5g, lane, mx);
    conv_g135<L, L / 2, L - L / 2>(sXu, w1g, w3g, w5g, lane, mx);
  } else if constexpr (L <= 16) {
    conv_g135<L, 0, 8>(sXu, w1g, w3g, w5g, lane, mx);
    conv_g135<L, 8, L - 8>(sXu, w1g, w3g, w5g, lane, mx);
  } else {
    conv_g135<L, 0, 6>(sXu, w1g, w3g, w5g, lane, mx);
    conv_g135<L, 6, 6>(sXu, w1g, w3g, w5g, lane, mx);
    conv_g135<L, 12, L - 12>(sXu, w1g, w3g, w5g, lane, mx);
  }
}
template<int L>
__device__ __forceinline__ void conv79_all(const ull* sXu, const ull* w7g,
                                           const ull* w9g, int lane,
                                           float (&mx)[10]) {
  if constexpr (L <= 9) {
    conv_g79<L, 0, L>(sXu, w7g, w9g, lane, mx);
  } else if constexpr (L <= 12) {
    conv_g79<L, 0, L / 2>(sXu, w7g, w9g, lane, mx);
    conv_g79<L, L / 2, L - L / 2>(sXu, w7g, w9g, lane, mx);
  } else if constexpr (L <= 16) {
    conv_g79<L, 0, 8>(sXu, w7g, w9g, lane, mx);
    conv_g79<L, 8, L - 8>(sXu, w7g, w9g, lane, mx);
  } else {
    conv_g79<L, 0, 9>(sXu, w7g, w9g, lane, mx);
    conv_g79<L, 9, L - 9>(sXu, w7g, w9g, lane, mx);
  }
}

template<int L, int S>
__device__ void do_seq(const ConvParams& p, float2* sX2,
                       int tid, int lane, int w, int bbase) {
  // stage x paired (x_b, x_{b+32}); /5 is folded into g_wdup
  const float* xg = p.seq[S];
  constexpr int CL = EMBED * L;
  for (int idx = tid; idx < CL * 32; idx += THREADS) {
    const int bp  = idx / CL;
    const int rem = idx - bp * CL;
    const int b0  = min(bbase + bp, p.B - 1);
    const int b1  = min(b0 + 32, p.B - 1);
    sX2[rem * 33 + bp] = make_float2(xg[(size_t)b0 * CL + rem],
                                     xg[(size_t)b1 * CL + rem]);
  }
  __syncthreads();
  const ull* sXu = (const ull*)sX2;
  const int bg0 = min(bbase + lane, p.B - 1);
  const int bg1 = min(bg0 + 32, p.B - 1);

  #pragma unroll
  for (int fi = 0; fi < 2; ++fi) {
    const int f = 2 * w + fi;
    float mx[10];
    #pragma unroll
    for (int i = 0; i < 10; ++i) mx[i] = 0.f;   // relu folded into init
    conv135_all<L>(sXu,
                   g_wdup + WOFF1 + (size_t)(S * 16 + f) * 20,
                   g_wdup + WOFF3 + (size_t)(S * 16 + f) * 60,
                   g_wdup + WOFF5 + (size_t)(S * 16 + f) * 100,
                   lane, mx);
    conv79_all<L>(sXu,
                  g_wdup + WOFF7 + (size_t)(S * 16 + f) * 140,
                  g_wdup + WOFF9 + (size_t)(S * 16 + f) * 180,
                  lane, mx);
    #pragma unroll
    for (int kidx = 0; kidx < 5; ++kidx) {
      g_feat[(size_t)(S * 80 + kidx * 16 + f) * p.B + bg0] = mx[kidx * 2];
      g_feat[(size_t)(S * 80 + kidx * 16 + f) * p.B + bg1] = mx[kidx * 2 + 1];
    }
  }
}

__global__ __launch_bounds__(THREADS, 2) void conv_kernel(ConvParams p) {
  extern __shared__ float smem[];
  float2* sX2 = (float2*)smem;
  const int tid   = threadIdx.x;
  const int lane  = tid & 31;
  const int w     = tid >> 5;          // warp -> filter pair
  const int bbase = blockIdx.x * 64;
  switch (blockIdx.y) {
    case 0: do_seq<12, 0>(p, sX2, tid, lane, w, bbase); break;
    case 1: do_seq< 7, 1>(p, sX2, tid, lane, w, bbase); break;
    case 2: do_seq< 8, 2>(p, sX2, tid, lane, w, bbase); break;
    case 3: do_seq<16, 3>(p, sX2, tid, lane, w, bbase); break;
    case 4: do_seq< 6, 4>(p, sX2, tid, lane, w, bbase); break;
    case 5: do_seq< 7, 5>(p, sX2, tid, lane, w, bbase); break;
    case 6: do_seq<18, 6>(p, sX2, tid, lane, w, bbase); break;
  }
}

// ---------------- prep kernels ----------------
__global__ void prep_wdup_kernel(const float* __restrict__ w1,
                                 const float* __restrict__ w3,
                                 const float* __restrict__ w5,
                                 const float* __restrict__ w7,
                                 const float* __restrict__ w9) {
  const int idx = blockIdx.x * 256 + threadIdx.x;
  if (idx >= 56000) return;
  float v;
  if      (idx < WOFF3) v = w1[idx - WOFF1];
  else if (idx < WOFF5) v = w3[idx - WOFF3];
  else if (idx < WOFF7) v = w5[idx - WOFF5];
  else if (idx < WOFF9) v = w7[idx - WOFF7];
  else                  v = w9[idx - WOFF9];
  v *= 0.2f;
  g_wdup[idx] = pack2(v, v);
}

__global__ void prep_w1_kernel(const float* __restrict__ w1) {
  const int idx = blockIdx.x * 256 + threadIdx.x;
  if (idx < FEAT * 32) {
    const int i   = idx >> 5;
    const int col = idx & 31;
    g_w1p[idx] = make_float2(w1[(size_t)(2 * col) * FEAT + i],
                             w1[(size_t)(2 * col + 1) * FEAT + i]);
  }
}

// ====== MLP v5: 128 batch/CTA, float4 feature loads, split-K halves ======
constexpr int MTHREADS = 512;
constexpr int MLP_SMEM_BYTES = 2 * 128 * 65 * 4;   // 66560

__global__ __launch_bounds__(MTHREADS) void mlp_kernel(MlpParams p) {
  extern __shared__ float smem[];
  float* sP1 = smem;              // [128][65] h=1 partials
  float* sH  = smem + 128 * 65;   // [128][65] sigmoid outputs
  const int tid  = threadIdx.x;
  const int lane = tid & 31;
  const int wid  = tid >> 5;      // 0..15
  const int h    = wid >> 3;      // feature half
  const int g    = wid & 7;       // hidden col group (8 cols)
  const int bbase = blockIdx.x * 128;
  const bool full = (bbase + 128 <= p.B);

  ull acc[4][4];                  // [col pair][batch i]
  #pragma unroll
  for (int pp = 0; pp < 4; ++pp) {
    const ull bia = (h == 0)
      ? pack2(p.lin1_b[g * 8 + 2 * pp], p.lin1_b[g * 8 + 2 * pp + 1])
      : 0ULL;
    #pragma unroll
    for (int bi = 0; bi < 4; ++bi) acc[pp][bi] = bia;
  }

  const float4* wbase = (const float4*)(g_w1p);
  const int i0 = h * 280;

  for (int oo = 0; oo < 280; oo += 4) {
    float4 fb[4];
    if (full) {
      #pragma unroll
      for (int k = 0; k < 4; ++k)
        fb[k] = __ldg((const float4*)(g_feat + (size_t)(i0 + oo + k) * p.B
                                      + bbase + lane * 4));
    } else {
      #pragma unroll
      for (int k = 0; k < 4; ++k) {
        float v[4];
        #pragma unroll
        for (int bi = 0; bi < 4; ++bi) {
          const int b = min(bbase + lane * 4 + bi, p.B - 1);
          v[bi] = g_feat[(size_t)(i0 + oo + k) * p.B + b];
        }
        fb[k] = make_float4(v[0], v[1], v[2], v[3]);
      }
    }
    #pragma unroll
    for (int k = 0; k < 4; ++k) {
      const int i = i0 + oo + k;
      const float4 wa = wbase[i * 16 + g * 2];      // uniform, L1-hot
      const float4 wb = wbase[i * 16 + g * 2 + 1];
      const ull w0 = pack2(wa.x, wa.y);
      const ull w1v = pack2(wa.z, wa.w);
      const ull w2 = pack2(wb.x, wb.y);
      const ull w3 = pack2(wb.z, wb.w);
      const float fv[4] = {fb[k].x, fb[k].y, fb[k].z, fb[k].w};
      #pragma unroll
      for (int bi = 0; bi < 4; ++bi) {
        const ull ff = pack2(fv[bi], fv[bi]);
        acc[0][bi] = fma2(ff, w0, acc[0][bi]);
        acc[1][bi] = fma2(ff, w1v, acc[1][bi]);
        acc[2][bi] = fma2(ff, w2, acc[2][bi]);
        acc[3][bi] = fma2(ff, w3, acc[3][bi]);
      }
    }
  }

  if (h == 1) {
    #pragma unroll
    for (int bi = 0; bi < 4; ++bi)
      #pragma unroll
      for (int pp = 0; pp < 4; ++pp) {
        float a, bb; unpack2(acc[pp][bi], a, bb);
        sP1[(lane * 4 + bi) * 65 + g * 8 + 2 * pp]     = a;
        sP1[(lane * 4 + bi) * 65 + g * 8 + 2 * pp + 1] = bb;
      }
  }
  __syncthreads();
  if (h == 0) {
    #pragma unroll
    for (int bi = 0; bi < 4; ++bi)
      #pragma unroll
      for (int pp = 0; pp < 4; ++pp) {
        float a, bb; unpack2(acc[pp][bi], a, bb);
        a  += sP1[(lane * 4 + bi) * 65 + g * 8 + 2 * pp];
        bb += sP1[(lane * 4 + bi) * 65 + g * 8 + 2 * pp + 1];
        sH[(lane * 4 + bi) * 65 + g * 8 + 2 * pp]     = 1.f / (1.f + __expf(-a));
        sH[(lane * 4 + bi) * 65 + g * 8 + 2 * pp + 1] = 1.f / (1.f + __expf(-bb));
      }
  }
  __syncthreads();

  if (tid < 128) {
    const int bgo = bbase + tid;
    if (bgo < p.B) {
      float o = p.lin2_b[0];
      #pragma unroll
      for (int j = 0; j < 64; ++j)
        o = fmaf(sH[tid * 65 + j], __ldg(p.lin2_w + j), o);
      p.out[bgo] = o;
    }
  }
}

} // namespace

extern "C" void kernel_launch(void* const* d_in, const int* in_sizes, int n_in,
                              void* d_out, int out_size) {
  ConvParams cp;
  for (int i = 0; i < 7; ++i) cp.seq[i] = (const float*)d_in[i];
  for (int j = 0; j < 5; ++j) cp.Wk[j] = (const float*)d_in[7 + j];
  cp.B = out_size;

  MlpParams mp;
  mp.lin1_w = (const float*)d_in[12];
  mp.lin1_b = (const float*)d_in[13];
  mp.lin2_w = (const float*)d_in[14];
  mp.lin2_b = (const float*)d_in[15];
  mp.out = (float*)d_out;
  mp.B   = out_size;

  static bool attr_set = false;
  if (!attr_set) {
    cudaFuncSetAttribute(conv_kernel,
                         cudaFuncAttributeMaxDynamicSharedMemorySize, CONV_SMEM_BYTES);
    cudaFuncSetAttribute(mlp_kernel,
                         cudaFuncAttributeMaxDynamicSharedMemorySize, MLP_SMEM_BYTES);
    attr_set = true;
  }

  const int tiles64  = (cp.B + 63) / 64;
  const int tiles128 = (cp.B + 127) / 128;
  prep_wdup_kernel<<<(56000 + 255) / 256, 256>>>(cp.Wk[0], cp.Wk[1], cp.Wk[2],
                                                 cp.Wk[3], cp.Wk[4]);
  prep_w1_kernel<<<(FEAT * 32 + 255) / 256, 256>>>(mp.lin1_w);
  dim3 cgrid(tiles64, 7);
  conv_kernel<<<cgrid, THREADS, CONV_SMEM_BYTES>>>(cp);
  mlp_kernel<<<tiles128, MTHREADS, MLP_SMEM_BYTES>>>(mp);
}